// round 4
// baseline (speedup 1.0000x reference)
#include <cuda_runtime.h>
#include <cuda_bf16.h>

// GraphConv: out = segment_sum(feat[src] -> dst) @ W_neigh + b_neigh + feat @ W_self
// N = 100000 nodes, D = 128, E = 600000 edges.
// NOTE: harness downcasts int64 indices to int32 — src/dst are const int*.

#define D_FEAT 128
#define N_NODES_MAX 100000

// Aggregation scratch (51.2 MB). float4 type guarantees 16-byte alignment for
// the vector RED and float4 stores. Device global = no allocation.
__device__ float4 g_agg4[(size_t)N_NODES_MAX * (D_FEAT / 4)];

// ---------------------------------------------------------------------------
// Kernel 1: zero the aggregation buffer.
// ---------------------------------------------------------------------------
__global__ void zero_agg_kernel(int total4) {
    int i = blockIdx.x * blockDim.x + threadIdx.x;
    float4 z = make_float4(0.f, 0.f, 0.f, 0.f);
    for (; i < total4; i += gridDim.x * blockDim.x) {
        g_agg4[i] = z;
    }
}

// ---------------------------------------------------------------------------
// Kernel 2: scatter-add. One warp per edge.
// Lane l: float4 l of feat[src] -> red.global.add.v4.f32 into g_agg[dst].
// ---------------------------------------------------------------------------
__global__ void scatter_kernel(const float* __restrict__ feat,
                               const int* __restrict__ src,
                               const int* __restrict__ dst,
                               int n_edges, int n_nodes) {
    int warps_per_block = blockDim.x >> 5;
    int e = blockIdx.x * warps_per_block + (threadIdx.x >> 5);
    if (e >= n_edges) return;
    int lane = threadIdx.x & 31;

    int s = src[e];
    int d = dst[e];
    // Defensive: never fault on a bad index (would surface as rel_err instead).
    if ((unsigned)s >= (unsigned)n_nodes || (unsigned)d >= (unsigned)n_nodes) return;

    const float4* fsrc = reinterpret_cast<const float4*>(feat) + (size_t)s * (D_FEAT / 4);
    float4 v = fsrc[lane];

    float4* dstp = g_agg4 + (size_t)d * (D_FEAT / 4) + lane;
    asm volatile("red.global.add.v4.f32 [%0], {%1, %2, %3, %4};"
                 :: "l"(dstp), "f"(v.x), "f"(v.y), "f"(v.z), "f"(v.w)
                 : "memory");
}

// ---------------------------------------------------------------------------
// Kernel 3: fused dual GEMM + bias.
//   out[m][n] = sum_k agg[m][k]*Wn[k][n] + sum_k feat[m][k]*Ws[k][n] + b[n]
// Tile: 128x128 per block, 256 threads, 8x8 per thread, TK=16.
// ---------------------------------------------------------------------------
#define TK 16
#define APAD 136  // 128 + 8 pad; 136 % 4 == 0 keeps float4-aligned smem reads

__global__ __launch_bounds__(256, 4)
void gemm_kernel(const float* __restrict__ feat,
                 const float* __restrict__ Wn,
                 const float* __restrict__ bn,
                 const float* __restrict__ Ws,
                 float* __restrict__ out,
                 int n_nodes) {
    __shared__ float As[TK][APAD];      // A tile, transposed: As[k][m]
    __shared__ float Wsm[TK][D_FEAT];   // W tile: Wsm[k][n]

    int tid = threadIdx.x;
    int tx = tid & 15;        // output col group -> cols tx*8..tx*8+7
    int ty = tid >> 4;        // output row group -> rows ty*8..ty*8+7
    int m0 = blockIdx.x * 128;

    float acc[8][8];
#pragma unroll
    for (int i = 0; i < 8; i++)
#pragma unroll
        for (int j = 0; j < 8; j++)
            acc[i][j] = 0.f;

    // A-load: thread -> row a_r, cols a_c..a_c+7
    int a_r = tid >> 1;
    int a_c = (tid & 1) * 8;
    // W-load: thread -> row w_r, cols w_c..w_c+7
    int w_r = tid >> 4;
    int w_c = (tid & 15) * 8;

    const float* aggf = reinterpret_cast<const float*>(g_agg4);

    for (int half = 0; half < 2; ++half) {
        const float* A = half ? feat : aggf;
        const float* W = half ? Ws : Wn;

        for (int kk = 0; kk < D_FEAT; kk += TK) {
            int grow = m0 + a_r;
            int growc = grow < n_nodes ? grow : (n_nodes - 1);  // clamp; stores guarded
            const float4* ap =
                reinterpret_cast<const float4*>(A + (size_t)growc * D_FEAT + kk + a_c);
            float4 av0 = ap[0];
            float4 av1 = ap[1];
            const float4* wp =
                reinterpret_cast<const float4*>(W + (size_t)(kk + w_r) * D_FEAT + w_c);
            float4 wv0 = wp[0];
            float4 wv1 = wp[1];

            __syncthreads();  // protect previous iteration's smem reads
            As[a_c + 0][a_r] = av0.x;
            As[a_c + 1][a_r] = av0.y;
            As[a_c + 2][a_r] = av0.z;
            As[a_c + 3][a_r] = av0.w;
            As[a_c + 4][a_r] = av1.x;
            As[a_c + 5][a_r] = av1.y;
            As[a_c + 6][a_r] = av1.z;
            As[a_c + 7][a_r] = av1.w;
            *reinterpret_cast<float4*>(&Wsm[w_r][w_c + 0]) = wv0;
            *reinterpret_cast<float4*>(&Wsm[w_r][w_c + 4]) = wv1;
            __syncthreads();

#pragma unroll
            for (int k = 0; k < TK; ++k) {
                float4 a0 = *reinterpret_cast<const float4*>(&As[k][ty * 8 + 0]);
                float4 a1 = *reinterpret_cast<const float4*>(&As[k][ty * 8 + 4]);
                float4 w0 = *reinterpret_cast<const float4*>(&Wsm[k][tx * 8 + 0]);
                float4 w1 = *reinterpret_cast<const float4*>(&Wsm[k][tx * 8 + 4]);
                float a[8] = {a0.x, a0.y, a0.z, a0.w, a1.x, a1.y, a1.z, a1.w};
                float w[8] = {w0.x, w0.y, w0.z, w0.w, w1.x, w1.y, w1.z, w1.w};
#pragma unroll
                for (int i = 0; i < 8; i++)
#pragma unroll
                    for (int j = 0; j < 8; j++)
                        acc[i][j] = fmaf(a[i], w[j], acc[i][j]);
            }
        }
    }

    // ---- bias + store ----
    float4 b0 = reinterpret_cast<const float4*>(bn)[tx * 2 + 0];
    float4 b1 = reinterpret_cast<const float4*>(bn)[tx * 2 + 1];
    float bv[8] = {b0.x, b0.y, b0.z, b0.w, b1.x, b1.y, b1.z, b1.w};

#pragma unroll
    for (int i = 0; i < 8; i++) {
        int row = m0 + ty * 8 + i;
        if (row < n_nodes) {
            float4 o0, o1;
            o0.x = acc[i][0] + bv[0];
            o0.y = acc[i][1] + bv[1];
            o0.z = acc[i][2] + bv[2];
            o0.w = acc[i][3] + bv[3];
            o1.x = acc[i][4] + bv[4];
            o1.y = acc[i][5] + bv[5];
            o1.z = acc[i][6] + bv[6];
            o1.w = acc[i][7] + bv[7];
            float4* op = reinterpret_cast<float4*>(out + (size_t)row * D_FEAT + tx * 8);
            op[0] = o0;
            op[1] = o1;
        }
    }
}

// ---------------------------------------------------------------------------
// Launch
// ---------------------------------------------------------------------------
extern "C" void kernel_launch(void* const* d_in, const int* in_sizes, int n_in,
                              void* d_out, int out_size) {
    const float* feat = (const float*)d_in[0];
    const int* src    = (const int*)d_in[1];   // int64 downcast to int32 by harness
    const int* dst    = (const int*)d_in[2];
    const float* Wn   = (const float*)d_in[3];
    const float* bn   = (const float*)d_in[4];
    const float* Ws   = (const float*)d_in[5];
    float* out        = (float*)d_out;

    int n_nodes = in_sizes[0] / D_FEAT;
    int n_edges = in_sizes[1];

    // 1) zero agg
    int total4 = n_nodes * (D_FEAT / 4);
    int zblocks = (total4 + 255) / 256;
    if (zblocks > 4096) zblocks = 4096;
    zero_agg_kernel<<<zblocks, 256>>>(total4);

    // 2) scatter-add (8 warps = 8 edges per block)
    int sblocks = (n_edges + 7) / 8;
    scatter_kernel<<<sblocks, 256>>>(feat, src, dst, n_edges, n_nodes);

    // 3) fused dual GEMM + bias
    int gblocks = (n_nodes + 127) / 128;
    gemm_kernel<<<gblocks, 256>>>(feat, Wn, bn, Ws, out, n_nodes);
}

// round 8
// speedup vs baseline: 3.7590x; 3.7590x over previous
#include <cuda_runtime.h>
#include <cuda_bf16.h>

// GraphConv: out = segment_sum(feat[src] -> dst) @ W_neigh + b_neigh + feat @ W_self
// N = 100000 nodes, D = 128, E = 600000 edges.
// Harness downcasts int64 indices to int32 — src/dst are const int*.

#define D_FEAT 128
#define N_NODES_MAX 100000

// Aggregation scratch (51.2 MB). float4 type guarantees 16-byte alignment.
__device__ float4 g_agg4[(size_t)N_NODES_MAX * (D_FEAT / 4)];

// ---------------------------------------------------------------------------
// Kernel 1: zero the aggregation buffer.
// ---------------------------------------------------------------------------
__global__ void zero_agg_kernel(int total4) {
    int i = blockIdx.x * blockDim.x + threadIdx.x;
    float4 z = make_float4(0.f, 0.f, 0.f, 0.f);
    for (; i < total4; i += gridDim.x * blockDim.x) {
        g_agg4[i] = z;
    }
}

// ---------------------------------------------------------------------------
// Kernel 2: scatter-add. One warp per edge.
// Lane l: float4 l of feat[src] -> red.global.add.v4.f32 into g_agg[dst].
// ---------------------------------------------------------------------------
__global__ void scatter_kernel(const float* __restrict__ feat,
                               const int* __restrict__ src,
                               const int* __restrict__ dst,
                               int n_edges, int n_nodes) {
    int warps_per_block = blockDim.x >> 5;
    int e = blockIdx.x * warps_per_block + (threadIdx.x >> 5);
    if (e >= n_edges) return;
    int lane = threadIdx.x & 31;

    int s = src[e];
    int d = dst[e];
    if ((unsigned)s >= (unsigned)n_nodes || (unsigned)d >= (unsigned)n_nodes) return;

    const float4* fsrc = reinterpret_cast<const float4*>(feat) + (size_t)s * (D_FEAT / 4);
    float4 v = fsrc[lane];

    float4* dstp = g_agg4 + (size_t)d * (D_FEAT / 4) + lane;
    asm volatile("red.global.add.v4.f32 [%0], {%1, %2, %3, %4};"
                 :: "l"(dstp), "f"(v.x), "f"(v.y), "f"(v.z), "f"(v.w)
                 : "memory");
}

// ---------------------------------------------------------------------------
// Kernel 3: fused dual GEMM + bias.
//   out[m][n] = sum_k agg[m][k]*Wn[k][n] + sum_k feat[m][k]*Ws[k][n] + b[n]
// Tile: 128x128 per block, 256 threads, 8x8 per thread, TK=16.
// NO min-blocks clamp: acc[8][8] + fragments needs ~128 regs; forcing 4
// blocks/SM (64 regs) caused massive local-memory spills in the FMA loop.
// ---------------------------------------------------------------------------
#define TK 16
#define APAD 136  // 128 + 8 pad; 136 % 4 == 0 keeps float4-aligned smem reads

__global__ __launch_bounds__(256)
void gemm_kernel(const float* __restrict__ feat,
                 const float* __restrict__ Wn,
                 const float* __restrict__ bn,
                 const float* __restrict__ Ws,
                 float* __restrict__ out,
                 int n_nodes) {
    __shared__ float As[TK][APAD];      // A tile, transposed: As[k][m]
    __shared__ float Wsm[TK][D_FEAT];   // W tile: Wsm[k][n]

    int tid = threadIdx.x;
    int tx = tid & 15;        // output col group -> cols tx*8..tx*8+7
    int ty = tid >> 4;        // output row group -> rows ty*8..ty*8+7
    int m0 = blockIdx.x * 128;

    float acc[8][8];
#pragma unroll
    for (int i = 0; i < 8; i++)
#pragma unroll
        for (int j = 0; j < 8; j++)
            acc[i][j] = 0.f;

    // A-load: thread -> row a_r, cols a_c..a_c+7
    int a_r = tid >> 1;
    int a_c = (tid & 1) * 8;
    // W-load: thread -> row w_r, cols w_c..w_c+7
    int w_r = tid >> 4;
    int w_c = (tid & 15) * 8;

    const float* aggf = reinterpret_cast<const float*>(g_agg4);

    for (int half = 0; half < 2; ++half) {
        const float* A = half ? feat : aggf;
        const float* W = half ? Ws : Wn;

        for (int kk = 0; kk < D_FEAT; kk += TK) {
            int grow = m0 + a_r;
            int growc = grow < n_nodes ? grow : (n_nodes - 1);  // clamp; stores guarded
            const float4* ap =
                reinterpret_cast<const float4*>(A + (size_t)growc * D_FEAT + kk + a_c);
            float4 av0 = ap[0];
            float4 av1 = ap[1];
            const float4* wp =
                reinterpret_cast<const float4*>(W + (size_t)(kk + w_r) * D_FEAT + w_c);
            float4 wv0 = wp[0];
            float4 wv1 = wp[1];

            __syncthreads();  // protect previous iteration's smem reads
            As[a_c + 0][a_r] = av0.x;
            As[a_c + 1][a_r] = av0.y;
            As[a_c + 2][a_r] = av0.z;
            As[a_c + 3][a_r] = av0.w;
            As[a_c + 4][a_r] = av1.x;
            As[a_c + 5][a_r] = av1.y;
            As[a_c + 6][a_r] = av1.z;
            As[a_c + 7][a_r] = av1.w;
            *reinterpret_cast<float4*>(&Wsm[w_r][w_c + 0]) = wv0;
            *reinterpret_cast<float4*>(&Wsm[w_r][w_c + 4]) = wv1;
            __syncthreads();

#pragma unroll
            for (int k = 0; k < TK; ++k) {
                float4 a0 = *reinterpret_cast<const float4*>(&As[k][ty * 8 + 0]);
                float4 a1 = *reinterpret_cast<const float4*>(&As[k][ty * 8 + 4]);
                float4 w0 = *reinterpret_cast<const float4*>(&Wsm[k][tx * 8 + 0]);
                float4 w1 = *reinterpret_cast<const float4*>(&Wsm[k][tx * 8 + 4]);
                float a[8] = {a0.x, a0.y, a0.z, a0.w, a1.x, a1.y, a1.z, a1.w};
                float w[8] = {w0.x, w0.y, w0.z, w0.w, w1.x, w1.y, w1.z, w1.w};
#pragma unroll
                for (int i = 0; i < 8; i++)
#pragma unroll
                    for (int j = 0; j < 8; j++)
                        acc[i][j] = fmaf(a[i], w[j], acc[i][j]);
            }
        }
    }

    // ---- bias + store ----
    float4 b0 = reinterpret_cast<const float4*>(bn)[tx * 2 + 0];
    float4 b1 = reinterpret_cast<const float4*>(bn)[tx * 2 + 1];
    float bv[8] = {b0.x, b0.y, b0.z, b0.w, b1.x, b1.y, b1.z, b1.w};

#pragma unroll
    for (int i = 0; i < 8; i++) {
        int row = m0 + ty * 8 + i;
        if (row < n_nodes) {
            float4 o0, o1;
            o0.x = acc[i][0] + bv[0];
            o0.y = acc[i][1] + bv[1];
            o0.z = acc[i][2] + bv[2];
            o0.w = acc[i][3] + bv[3];
            o1.x = acc[i][4] + bv[4];
            o1.y = acc[i][5] + bv[5];
            o1.z = acc[i][6] + bv[6];
            o1.w = acc[i][7] + bv[7];
            float4* op = reinterpret_cast<float4*>(out + (size_t)row * D_FEAT + tx * 8);
            op[0] = o0;
            op[1] = o1;
        }
    }
}

// ---------------------------------------------------------------------------
// Launch
// ---------------------------------------------------------------------------
extern "C" void kernel_launch(void* const* d_in, const int* in_sizes, int n_in,
                              void* d_out, int out_size) {
    const float* feat = (const float*)d_in[0];
    const int* src    = (const int*)d_in[1];   // int64 downcast to int32 by harness
    const int* dst    = (const int*)d_in[2];
    const float* Wn   = (const float*)d_in[3];
    const float* bn   = (const float*)d_in[4];
    const float* Ws   = (const float*)d_in[5];
    float* out        = (float*)d_out;

    int n_nodes = in_sizes[0] / D_FEAT;
    int n_edges = in_sizes[1];

    // 1) zero agg
    int total4 = n_nodes * (D_FEAT / 4);
    int zblocks = (total4 + 255) / 256;
    if (zblocks > 4096) zblocks = 4096;
    zero_agg_kernel<<<zblocks, 256>>>(total4);

    // 2) scatter-add (8 warps = 8 edges per block)
    int sblocks = (n_edges + 7) / 8;
    scatter_kernel<<<sblocks, 256>>>(feat, src, dst, n_edges, n_nodes);

    // 3) fused dual GEMM + bias
    int gblocks = (n_nodes + 127) / 128;
    gemm_kernel<<<gblocks, 256>>>(feat, Wn, bn, Ws, out, n_nodes);
}

// round 10
// speedup vs baseline: 5.5865x; 1.4862x over previous
#include <cuda_runtime.h>
#include <cuda_bf16.h>
#include <cstdint>

// GraphConv: out = segment_sum(feat[src] -> dst) @ W_neigh + b_neigh + feat @ W_self
// N = 100000 nodes, D = 128, E = 600000 edges.
// Harness downcasts int64 indices to int32 — src/dst are const int*.

#define D_FEAT 128
#define N_NODES_MAX 100000

// Aggregation scratch (51.2 MB). float4 type guarantees 16-byte alignment.
__device__ float4 g_agg4[(size_t)N_NODES_MAX * (D_FEAT / 4)];

// ---------------------------------------------------------------------------
// Kernel 1: zero the aggregation buffer.
// ---------------------------------------------------------------------------
__global__ void zero_agg_kernel(int total4) {
    int i = blockIdx.x * blockDim.x + threadIdx.x;
    float4 z = make_float4(0.f, 0.f, 0.f, 0.f);
    for (; i < total4; i += gridDim.x * blockDim.x) {
        g_agg4[i] = z;
    }
}

// ---------------------------------------------------------------------------
// Kernel 2: scatter-add. One warp per edge; vector RED into L2-resident agg.
// ---------------------------------------------------------------------------
__global__ void scatter_kernel(const float* __restrict__ feat,
                               const int* __restrict__ src,
                               const int* __restrict__ dst,
                               int n_edges, int n_nodes) {
    int warps_per_block = blockDim.x >> 5;
    int e = blockIdx.x * warps_per_block + (threadIdx.x >> 5);
    if (e >= n_edges) return;
    int lane = threadIdx.x & 31;

    int s = src[e];
    int d = dst[e];
    if ((unsigned)s >= (unsigned)n_nodes || (unsigned)d >= (unsigned)n_nodes) return;

    const float4* fsrc = reinterpret_cast<const float4*>(feat) + (size_t)s * (D_FEAT / 4);
    float4 v = fsrc[lane];

    float4* dstp = g_agg4 + (size_t)d * (D_FEAT / 4) + lane;
    asm volatile("red.global.add.v4.f32 [%0], {%1, %2, %3, %4};"
                 :: "l"(dstp), "f"(v.x), "f"(v.y), "f"(v.z), "f"(v.w)
                 : "memory");
}

// ---------------------------------------------------------------------------
// Kernel 3: split-bf16 tensor-core dual GEMM + bias.
//   out = agg@Wn + feat@Ws + b, fp32 via 3-term bf16 split:
//   A@W ~= Ahi@Whi + Ahi@Wlo + Alo@Whi   (lo*lo ~ 4e-6 rel, dropped)
// Block: 128x128 output tile, 256 threads (8 warps, 2 m-groups x 4 n-groups).
// Whole K=128 staged in smem as padded bf16 hi/lo tiles for A and W.
// ---------------------------------------------------------------------------
#define ASTRIDE 136            // bf16 elems per padded row (272 B: kills ldmatrix conflicts)
#define TILE_BF16 (128 * ASTRIDE)
#define GEMM_SMEM_BYTES (4 * TILE_BF16 * 2)   // Ahi, Alo, Whi, Wlo = 139264 B

__device__ __forceinline__ uint32_t smem_u32(const void* p) {
    return (uint32_t)__cvta_generic_to_shared(p);
}

__device__ __forceinline__ void ldm_x4(uint32_t* r, uint32_t addr) {
    asm volatile("ldmatrix.sync.aligned.m8n8.x4.shared.b16 {%0,%1,%2,%3}, [%4];"
                 : "=r"(r[0]), "=r"(r[1]), "=r"(r[2]), "=r"(r[3]) : "r"(addr));
}

__device__ __forceinline__ void ldm_x4_trans(uint32_t* r, uint32_t addr) {
    asm volatile("ldmatrix.sync.aligned.m8n8.x4.trans.shared.b16 {%0,%1,%2,%3}, [%4];"
                 : "=r"(r[0]), "=r"(r[1]), "=r"(r[2]), "=r"(r[3]) : "r"(addr));
}

__device__ __forceinline__ void mma16816(float* c, const uint32_t* a, const uint32_t* b) {
    asm volatile("mma.sync.aligned.m16n8k16.row.col.f32.bf16.bf16.f32 "
                 "{%0,%1,%2,%3}, {%4,%5,%6,%7}, {%8,%9}, {%0,%1,%2,%3};"
                 : "+f"(c[0]), "+f"(c[1]), "+f"(c[2]), "+f"(c[3])
                 : "r"(a[0]), "r"(a[1]), "r"(a[2]), "r"(a[3]), "r"(b[0]), "r"(b[1]));
}

// pack two floats as bf16x2: low half = e0, high half = e1
__device__ __forceinline__ uint32_t packbf2(float e0, float e1) {
    uint32_t r;
    asm("cvt.rn.bf16x2.f32 %0, %1, %2;" : "=r"(r) : "f"(e1), "f"(e0));
    return r;
}

__device__ __forceinline__ float bf16_round(float x) {
    return __bfloat162float(__float2bfloat16_rn(x));
}

__global__ __launch_bounds__(256)
void gemm_kernel(const float* __restrict__ feat,
                 const float* __restrict__ Wn,
                 const float* __restrict__ bn,
                 const float* __restrict__ Ws,
                 float* __restrict__ out,
                 int n_nodes) {
    extern __shared__ char smem[];
    __nv_bfloat16* Ahi = reinterpret_cast<__nv_bfloat16*>(smem);
    __nv_bfloat16* Alo = Ahi + TILE_BF16;
    __nv_bfloat16* Whi = Alo + TILE_BF16;
    __nv_bfloat16* Wlo = Whi + TILE_BF16;

    const uint32_t aHi_b = smem_u32(Ahi);
    const uint32_t aLo_b = smem_u32(Alo);
    const uint32_t wHi_b = smem_u32(Whi);
    const uint32_t wLo_b = smem_u32(Wlo);

    int tid = threadIdx.x;
    int lane = tid & 31;
    int wid = tid >> 5;
    int wm = wid & 1;          // m-group: rows wm*64 .. +63
    int wn = wid >> 1;         // n-group: cols wn*32 .. +31
    int m0 = blockIdx.x * 128;

    int lrow = lane & 15;
    int lcolh = (lane >> 4) << 3;  // 0 or 8

    const float* aggf = reinterpret_cast<const float*>(g_agg4);

    float acc[4][4][4];
#pragma unroll
    for (int mi = 0; mi < 4; mi++)
#pragma unroll
        for (int ni = 0; ni < 4; ni++)
#pragma unroll
            for (int q = 0; q < 4; q++)
                acc[mi][ni][q] = 0.f;

    for (int half = 0; half < 2; ++half) {
        const float* Aglob = half ? feat : aggf;
        const float* Wglob = half ? Ws : Wn;

        __syncthreads();  // previous half's smem reads done
        // ---- convert A and W tiles to hi/lo bf16 in smem ----
#pragma unroll 4
        for (int it = 0; it < 16; ++it) {
            int idx4 = it * 256 + tid;        // float4 index, 0..4095
            int row = idx4 >> 5;              // 0..127
            int col = (idx4 & 31) << 2;       // 0..124 step 4

            int grow = m0 + row;
            if (grow >= n_nodes) grow = n_nodes - 1;  // clamp; stores guarded
            float4 v = *reinterpret_cast<const float4*>(Aglob + (size_t)grow * 128 + col);
            float h0 = bf16_round(v.x), h1 = bf16_round(v.y);
            float h2 = bf16_round(v.z), h3 = bf16_round(v.w);
            uint2 hp = make_uint2(packbf2(h0, h1), packbf2(h2, h3));
            uint2 lp = make_uint2(packbf2(v.x - h0, v.y - h1),
                                  packbf2(v.z - h2, v.w - h3));
            int so = row * ASTRIDE + col;
            *reinterpret_cast<uint2*>(Ahi + so) = hp;
            *reinterpret_cast<uint2*>(Alo + so) = lp;

            float4 w = *reinterpret_cast<const float4*>(Wglob + (size_t)row * 128 + col);
            float g0 = bf16_round(w.x), g1 = bf16_round(w.y);
            float g2 = bf16_round(w.z), g3 = bf16_round(w.w);
            uint2 whp = make_uint2(packbf2(g0, g1), packbf2(g2, g3));
            uint2 wlp = make_uint2(packbf2(w.x - g0, w.y - g1),
                                   packbf2(w.z - g2, w.w - g3));
            *reinterpret_cast<uint2*>(Whi + so) = whp;
            *reinterpret_cast<uint2*>(Wlo + so) = wlp;
        }
        __syncthreads();

        // ---- tensor-core compute over K=128 ----
#pragma unroll
        for (int ks = 0; ks < 8; ++ks) {
            int k0 = ks * 16;

            uint32_t ahi[4][4], alo[4][4];
#pragma unroll
            for (int mi = 0; mi < 4; ++mi) {
                uint32_t off = (uint32_t)((wm * 64 + mi * 16 + lrow) * ASTRIDE + k0 + lcolh) * 2;
                ldm_x4(ahi[mi], aHi_b + off);
                ldm_x4(alo[mi], aLo_b + off);
            }
            uint32_t bhi[4][2], blo[4][2];
#pragma unroll
            for (int nh = 0; nh < 2; ++nh) {
                uint32_t off = (uint32_t)((k0 + lrow) * ASTRIDE + wn * 32 + nh * 16 + lcolh) * 2;
                uint32_t t[4];
                ldm_x4_trans(t, wHi_b + off);
                bhi[2 * nh][0] = t[0]; bhi[2 * nh][1] = t[1];
                bhi[2 * nh + 1][0] = t[2]; bhi[2 * nh + 1][1] = t[3];
                ldm_x4_trans(t, wLo_b + off);
                blo[2 * nh][0] = t[0]; blo[2 * nh][1] = t[1];
                blo[2 * nh + 1][0] = t[2]; blo[2 * nh + 1][1] = t[3];
            }
#pragma unroll
            for (int mi = 0; mi < 4; ++mi)
#pragma unroll
                for (int ni = 0; ni < 4; ++ni) {
                    mma16816(acc[mi][ni], ahi[mi], bhi[ni]);
                    mma16816(acc[mi][ni], ahi[mi], blo[ni]);
                    mma16816(acc[mi][ni], alo[mi], bhi[ni]);
                }
        }
    }

    // ---- bias + store (fragment layout: rows g, g+8; cols 2tg, 2tg+1) ----
    int g = lane >> 2, tg = lane & 3;
#pragma unroll
    for (int ni = 0; ni < 4; ++ni) {
        int col = wn * 32 + ni * 8 + 2 * tg;
        float2 bv = *reinterpret_cast<const float2*>(bn + col);
#pragma unroll
        for (int mi = 0; mi < 4; ++mi) {
            int r0 = m0 + wm * 64 + mi * 16 + g;
            if (r0 < n_nodes) {
                float2 o = make_float2(acc[mi][ni][0] + bv.x, acc[mi][ni][1] + bv.y);
                *reinterpret_cast<float2*>(out + (size_t)r0 * 128 + col) = o;
            }
            int r1 = r0 + 8;
            if (r1 < n_nodes) {
                float2 o = make_float2(acc[mi][ni][2] + bv.x, acc[mi][ni][3] + bv.y);
                *reinterpret_cast<float2*>(out + (size_t)r1 * 128 + col) = o;
            }
        }
    }
}

// ---------------------------------------------------------------------------
// Launch
// ---------------------------------------------------------------------------
extern "C" void kernel_launch(void* const* d_in, const int* in_sizes, int n_in,
                              void* d_out, int out_size) {
    const float* feat = (const float*)d_in[0];
    const int* src    = (const int*)d_in[1];   // int64 downcast to int32 by harness
    const int* dst    = (const int*)d_in[2];
    const float* Wn   = (const float*)d_in[3];
    const float* bn   = (const float*)d_in[4];
    const float* Ws   = (const float*)d_in[5];
    float* out        = (float*)d_out;

    int n_nodes = in_sizes[0] / D_FEAT;
    int n_edges = in_sizes[1];

    // 1) zero agg
    int total4 = n_nodes * (D_FEAT / 4);
    int zblocks = (total4 + 255) / 256;
    if (zblocks > 4096) zblocks = 4096;
    zero_agg_kernel<<<zblocks, 256>>>(total4);

    // 2) scatter-add (8 warps = 8 edges per block)
    int sblocks = (n_edges + 7) / 8;
    scatter_kernel<<<sblocks, 256>>>(feat, src, dst, n_edges, n_nodes);

    // 3) split-bf16 tensor-core dual GEMM + bias (139 KB dynamic smem)
    static bool attr_set = false;
    if (!attr_set) {
        cudaFuncSetAttribute(gemm_kernel,
                             cudaFuncAttributeMaxDynamicSharedMemorySize,
                             GEMM_SMEM_BYTES);
        attr_set = true;
    }
    int gblocks = (n_nodes + 127) / 128;
    gemm_kernel<<<gblocks, 256, GEMM_SMEM_BYTES>>>(feat, Wn, bn, Ws, out, n_nodes);
}